// round 15
// baseline (speedup 1.0000x reference)
#include <cuda_runtime.h>
#include <cuda_bf16.h>
#include <cstdint>
#include <cstring>

// AFM fused kernel: legacy mma.sync bf16 (3-term split), 256 threads, 2 CTAs/SM,
// B (W) fragments register-resident: 8 n-warps x (32m x 16n), preloaded once.
// One CTA per batch element. B=1024, F=33 (P=528 pairs), D=A=128.

#define F_   33
#define D_   128
#define A_   128
#define P_   528
#define THREADS_ 256
#define MT   32
#define NT_TILES 17
#define SA   136          // bf16 row stride (272B; LDSM rows hit distinct 16B sub-banks)

struct alignas(16) Smem {
    __nv_bfloat16 A_hi[MT * SA];
    __nv_bfloat16 A_lo[MT * SA];
    __nv_bfloat16 W_hi[A_ * SA];
    __nv_bfloat16 W_lo[A_ * SA];
    float xs[F_][132];
    float scores[P_];
    float gnn_s[A_];
    float bias_s[A_];
    float part[256];
    float red[16];
    unsigned short pairs[P_];
};

static __device__ __forceinline__ uint32_t smem_u32(const void* p) {
    uint32_t a;
    asm("{ .reg .u64 t; cvta.to.shared.u64 t, %1; cvt.u32.u64 %0, t; }" : "=r"(a) : "l"(p));
    return a;
}

#define LDSM_X4(r0, r1, r2, r3, addr) \
    asm volatile("ldmatrix.sync.aligned.m8n8.x4.shared.b16 {%0,%1,%2,%3}, [%4];" \
        : "=r"(r0), "=r"(r1), "=r"(r2), "=r"(r3) : "r"(addr))

static __device__ __forceinline__ void mma_bf16(float* c, const uint32_t* a,
                                                uint32_t b0, uint32_t b1) {
    asm("mma.sync.aligned.m16n8k16.row.col.f32.bf16.bf16.f32 "
        "{%0,%1,%2,%3}, {%4,%5,%6,%7}, {%8,%9}, {%0,%1,%2,%3};"
        : "+f"(c[0]), "+f"(c[1]), "+f"(c[2]), "+f"(c[3])
        : "r"(a[0]), "r"(a[1]), "r"(a[2]), "r"(a[3]), "r"(b0), "r"(b1));
}

// bf16 hi/lo split of 2 packed floats (packed along k)
static __device__ __forceinline__ void bf16_split2(float a, float b, uint32_t& h, uint32_t& l) {
    __nv_bfloat162 hh = __float22bfloat162_rn(make_float2(a, b));
    float2 hf = __bfloat1622float2(hh);
    __nv_bfloat162 ll = __float22bfloat162_rn(make_float2(a - hf.x, b - hf.y));
    h = *reinterpret_cast<uint32_t*>(&hh);
    l = *reinterpret_cast<uint32_t*>(&ll);
}

__global__ void __launch_bounds__(THREADS_, 2)
afm_kernel(const float* __restrict__ gnn,
           const float* __restrict__ x,
           const float* __restrict__ W,
           const float* __restrict__ bias,
           float* __restrict__ out)
{
    extern __shared__ unsigned char smem_raw[];
    Smem* s = reinterpret_cast<Smem*>(smem_raw);

    const int b    = blockIdx.x;
    const int tid  = threadIdx.x;
    const int lane = tid & 31;
    const int wid  = tid >> 5;         // 0..7 = n-subtile (16 cols each)
    const int rq   = lane >> 2;        // 0..7  (fragment row)
    const int kq   = 2 * (lane & 3);   // 0,2,4,6 (fragment col pair)

    // ---- pair table + zero scores ----
    for (int p = tid; p < P_; p += THREADS_) {
        int i = 0, base = 0;
        while (base + (F_ - 1 - i) <= p) { base += F_ - 1 - i; ++i; }
        int j = i + 1 + (p - base);
        s->pairs[p] = (unsigned short)((i << 8) | j);
        s->scores[p] = 0.f;
    }
    // ---- x[b] to smem ----
    const float4* xb = reinterpret_cast<const float4*>(x + (size_t)b * F_ * D_);
    for (int e = tid; e < F_ * D_ / 4; e += THREADS_) {
        int f = e >> 5, q = e & 31;
        *reinterpret_cast<float4*>(&s->xs[f][q * 4]) = xb[e];
    }
    if (tid < A_) {
        s->gnn_s[tid]  = gnn[(size_t)b * A_ + tid];
        s->bias_s[tid] = bias[tid];
    }
    // ---- W hi/lo bf16 tiles: W native [a][k], k-contiguous ----
    for (int e = tid; e < A_ * 16; e += THREADS_) {
        int a = e >> 4, kseg = e & 15, k0 = kseg * 8;
        const float4* wp = reinterpret_cast<const float4*>(W + a * D_ + k0);
        float4 w0 = wp[0], w1 = wp[1];
        uint4 hv, lv;
        bf16_split2(w0.x, w0.y, hv.x, lv.x);
        bf16_split2(w0.z, w0.w, hv.y, lv.y);
        bf16_split2(w1.x, w1.y, hv.z, lv.z);
        bf16_split2(w1.z, w1.w, hv.w, lv.w);
        *reinterpret_cast<uint4*>(&s->W_hi[a * SA + k0]) = hv;
        *reinterpret_cast<uint4*>(&s->W_lo[a * SA + k0]) = lv;
    }
    __syncthreads();

    // ---- preload this warp's B fragments (16n x 128k, hi+lo) into registers ----
    // B x4 covers 16n x 16k: lanes 0-7 n+0..7 @k0 | 8-15 n+0..7 @k0+8
    //                      | 16-23 n+8..15 @k0 | 24-31 n+8..15 @k0+8
    const int brow = wid * 16 + (lane & 7) + 8 * (lane >> 4);
    const int bkb  = 8 * ((lane >> 3) & 1);
    const uint32_t bWhi0 = smem_u32(&s->W_hi[brow * SA + bkb]);
    const uint32_t bWlo0 = smem_u32(&s->W_lo[brow * SA + bkb]);
    uint32_t Bh[8][4], Bl[8][4];
#pragma unroll
    for (int ks = 0; ks < 8; ++ks) {
        LDSM_X4(Bh[ks][0], Bh[ks][1], Bh[ks][2], Bh[ks][3], bWhi0 + ks * 32);
        LDSM_X4(Bl[ks][0], Bl[ks][1], Bl[ks][2], Bl[ks][3], bWlo0 + ks * 32);
    }

    // ---- A ldmatrix base addresses ----
    // A x4 covers 16m x 16k; second mf adds +16 rows.
    const int arow = (lane & 15);
    const int akb  = 8 * (lane >> 4);
    const uint32_t aAhi0 = smem_u32(&s->A_hi[arow * SA + akb]);
    const uint32_t aAlo0 = smem_u32(&s->A_lo[arow * SA + akb]);
    const uint32_t STEP16 = 16 * SA * 2;   // +16 rows, bytes

    // ==== main loop over 17 M-tiles of 32 pairs ====
    for (int t = 0; t < NT_TILES; ++t) {
        const int m0 = t * MT;
        __syncthreads();   // prior tile's A reads complete

        // ---- fill inner tile hi/lo: A[mloc][k] = xs[i][k]*xs[j][k] ----
        for (int e = tid; e < MT * 16; e += THREADS_) {
            int mloc = e >> 4, kseg = e & 15, k0 = kseg * 8;
            int m = m0 + mloc;
            uint4 hv = make_uint4(0, 0, 0, 0), lv = make_uint4(0, 0, 0, 0);
            if (m < P_) {
                unsigned short pr = s->pairs[m];
                const float4* xi = reinterpret_cast<const float4*>(&s->xs[pr >> 8][k0]);
                const float4* xj = reinterpret_cast<const float4*>(&s->xs[pr & 255][k0]);
                float4 a0 = xi[0], a1 = xi[1], c0 = xj[0], c1 = xj[1];
                bf16_split2(a0.x * c0.x, a0.y * c0.y, hv.x, lv.x);
                bf16_split2(a0.z * c0.z, a0.w * c0.w, hv.y, lv.y);
                bf16_split2(a1.x * c1.x, a1.y * c1.y, hv.z, lv.z);
                bf16_split2(a1.z * c1.z, a1.w * c1.w, hv.w, lv.w);
            }
            *reinterpret_cast<uint4*>(&s->A_hi[mloc * SA + k0]) = hv;
            *reinterpret_cast<uint4*>(&s->A_lo[mloc * SA + k0]) = lv;
        }
        __syncthreads();

        // ---- warp GEMM: 32m x 16n, B from registers ----
        float acc[2][2][4];   // [mf][nf][quad]
#pragma unroll
        for (int mf = 0; mf < 2; ++mf)
#pragma unroll
            for (int nf = 0; nf < 2; ++nf)
#pragma unroll
                for (int q = 0; q < 4; ++q) acc[mf][nf][q] = 0.f;

#pragma unroll
        for (int ks = 0; ks < 8; ++ks) {
            const uint32_t kb = ks * 32;   // 16 bf16 = 32 bytes
            uint32_t ah[2][4], al[2][4];
            LDSM_X4(ah[0][0], ah[0][1], ah[0][2], ah[0][3], aAhi0 + kb);
            LDSM_X4(ah[1][0], ah[1][1], ah[1][2], ah[1][3], aAhi0 + STEP16 + kb);
            LDSM_X4(al[0][0], al[0][1], al[0][2], al[0][3], aAlo0 + kb);
            LDSM_X4(al[1][0], al[1][1], al[1][2], al[1][3], aAlo0 + STEP16 + kb);
#pragma unroll
            for (int mf = 0; mf < 2; ++mf)
#pragma unroll
                for (int nf = 0; nf < 2; ++nf) {
                    mma_bf16(acc[mf][nf], ah[mf], Bh[ks][2 * nf], Bh[ks][2 * nf + 1]);
                    mma_bf16(acc[mf][nf], ah[mf], Bl[ks][2 * nf], Bl[ks][2 * nf + 1]);
                    mma_bf16(acc[mf][nf], al[mf], Bh[ks][2 * nf], Bh[ks][2 * nf + 1]);
                }
        }

        // ---- epilogue: bias + relu + gnn dot over this warp's 16 cols ----
#pragma unroll
        for (int mf = 0; mf < 2; ++mf) {
            float sc[2] = {0.f, 0.f};
#pragma unroll
            for (int nf = 0; nf < 2; ++nf) {
                const int n0 = wid * 16 + nf * 8 + kq;
                float g0 = s->gnn_s[n0], g1 = s->gnn_s[n0 + 1];
                float b0 = s->bias_s[n0], b1 = s->bias_s[n0 + 1];
                sc[0] = fmaf(g0, fmaxf(acc[mf][nf][0] + b0, 0.f), sc[0]);
                sc[0] = fmaf(g1, fmaxf(acc[mf][nf][1] + b1, 0.f), sc[0]);
                sc[1] = fmaf(g0, fmaxf(acc[mf][nf][2] + b0, 0.f), sc[1]);
                sc[1] = fmaf(g1, fmaxf(acc[mf][nf][3] + b1, 0.f), sc[1]);
            }
            sc[0] += __shfl_xor_sync(0xffffffffu, sc[0], 1);
            sc[0] += __shfl_xor_sync(0xffffffffu, sc[0], 2);
            sc[1] += __shfl_xor_sync(0xffffffffu, sc[1], 1);
            sc[1] += __shfl_xor_sync(0xffffffffu, sc[1], 2);
            if ((lane & 3) == 0) {
                int ma = m0 + mf * 16 + rq;   // 8 n-warps add per row
                if (ma < P_)     atomicAdd(&s->scores[ma],     sc[0]);
                if (ma + 8 < P_) atomicAdd(&s->scores[ma + 8], sc[1]);
            }
        }
    }
    __syncthreads();

    // ==== softmax over scores[528] ====
    float lmax = -1e30f;
    for (int p = tid; p < P_; p += THREADS_) lmax = fmaxf(lmax, s->scores[p]);
#pragma unroll
    for (int o = 16; o; o >>= 1) lmax = fmaxf(lmax, __shfl_xor_sync(0xffffffffu, lmax, o));
    if (lane == 0) s->red[wid] = lmax;
    __syncthreads();
    if (tid < 32) {
        float v = (tid < 8) ? s->red[tid] : -1e30f;
#pragma unroll
        for (int o = 4; o; o >>= 1) v = fmaxf(v, __shfl_xor_sync(0xffffffffu, v, o));
        if (tid == 0) s->red[8] = v;
    }
    __syncthreads();
    const float mx = s->red[8];

    float lsum = 0.f;
    for (int p = tid; p < P_; p += THREADS_) {
        float e = __expf(s->scores[p] - mx);
        s->scores[p] = e;
        lsum += e;
    }
#pragma unroll
    for (int o = 16; o; o >>= 1) lsum += __shfl_xor_sync(0xffffffffu, lsum, o);
    if (lane == 0) s->red[wid] = lsum;
    __syncthreads();
    if (tid < 32) {
        float v = (tid < 8) ? s->red[tid] : 0.f;
#pragma unroll
        for (int o = 4; o; o >>= 1) v += __shfl_xor_sync(0xffffffffu, v, o);
        if (tid == 0) s->red[9] = v;
    }
    __syncthreads();
    const float scale = 100.f / s->red[9];

    // ==== attn_output[d] = scale * sum_p exp_p * xs[i][d]*xs[j][d] ====
    const int d    = tid & 127;
    const int half = tid >> 7;
    float accd = 0.f;
    const int pstart = half * (P_ / 2);
    for (int p = pstart; p < pstart + P_ / 2; ++p) {
        unsigned short pr = s->pairs[p];
        accd = fmaf(s->scores[p], s->xs[pr >> 8][d] * s->xs[pr & 255][d], accd);
    }
    s->part[half * 128 + d] = accd;
    __syncthreads();

    float* outb = out + (size_t)b * (A_ + D_);
    if (tid < 128) {
        outb[tid]       = s->gnn_s[tid];
        outb[128 + tid] = (s->part[tid] + s->part[128 + tid]) * scale;
    }
}

extern "C" void kernel_launch(void* const* d_in, const int* in_sizes, int n_in,
                              void* d_out, int out_size)
{
    const float* gnn  = (const float*)d_in[0];   // [B, 128]
    const float* x    = (const float*)d_in[1];   // [B, 33, 128]
    const float* W    = (const float*)d_in[2];   // [128, 128]
    const float* bias = (const float*)d_in[3];   // [128]
    float* out        = (float*)d_out;           // [B, 256]

    const int B = in_sizes[0] / A_;
    const int smem_bytes = (int)sizeof(Smem);

    cudaFuncSetAttribute(afm_kernel, cudaFuncAttributeMaxDynamicSharedMemorySize, smem_bytes);
    afm_kernel<<<B, THREADS_, smem_bytes>>>(gnn, x, W, bias, out);
}

// round 16
// speedup vs baseline: 1.4989x; 1.4989x over previous
#include <cuda_runtime.h>
#include <cuda_bf16.h>
#include <cstdint>
#include <cstring>

// AFM fused kernel: legacy mma.sync bf16 (3-term split), 256 threads,
// 2 CTAs/SM with CTA-parity tile-order skew for cross-CTA phase overlap.
// One CTA per batch element. B=1024, F=33 (P=528 pairs), D=A=128.

#define F_   33
#define D_   128
#define A_   128
#define P_   528
#define THREADS_ 256
#define MT   32
#define NT_TILES 17
#define SA   136          // bf16 row stride (272B; LDSM rows hit distinct 16B sub-banks)

struct alignas(16) Smem {
    __nv_bfloat16 A_hi[MT * SA];
    __nv_bfloat16 A_lo[MT * SA];
    __nv_bfloat16 W_hi[A_ * SA];
    __nv_bfloat16 W_lo[A_ * SA];
    float xs[F_][132];
    float scores[P_];
    float gnn_s[A_];
    float bias_s[A_];
    float part[256];
    float red[16];
    unsigned short pairs[P_];
};

static __device__ __forceinline__ uint32_t smem_u32(const void* p) {
    uint32_t a;
    asm("{ .reg .u64 t; cvta.to.shared.u64 t, %1; cvt.u32.u64 %0, t; }" : "=r"(a) : "l"(p));
    return a;
}

#define LDSM_X4(r0, r1, r2, r3, addr) \
    asm volatile("ldmatrix.sync.aligned.m8n8.x4.shared.b16 {%0,%1,%2,%3}, [%4];" \
        : "=r"(r0), "=r"(r1), "=r"(r2), "=r"(r3) : "r"(addr))

static __device__ __forceinline__ void mma_bf16(float* c, const uint32_t* a,
                                                uint32_t b0, uint32_t b1) {
    asm("mma.sync.aligned.m16n8k16.row.col.f32.bf16.bf16.f32 "
        "{%0,%1,%2,%3}, {%4,%5,%6,%7}, {%8,%9}, {%0,%1,%2,%3};"
        : "+f"(c[0]), "+f"(c[1]), "+f"(c[2]), "+f"(c[3])
        : "r"(a[0]), "r"(a[1]), "r"(a[2]), "r"(a[3]), "r"(b0), "r"(b1));
}

// bf16 hi/lo split of 2 packed floats (packed along k)
static __device__ __forceinline__ void bf16_split2(float a, float b, uint32_t& h, uint32_t& l) {
    __nv_bfloat162 hh = __float22bfloat162_rn(make_float2(a, b));
    float2 hf = __bfloat1622float2(hh);
    __nv_bfloat162 ll = __float22bfloat162_rn(make_float2(a - hf.x, b - hf.y));
    h = *reinterpret_cast<uint32_t*>(&hh);
    l = *reinterpret_cast<uint32_t*>(&ll);
}

__global__ void __launch_bounds__(THREADS_, 2)
afm_kernel(const float* __restrict__ gnn,
           const float* __restrict__ x,
           const float* __restrict__ W,
           const float* __restrict__ bias,
           float* __restrict__ out)
{
    extern __shared__ unsigned char smem_raw[];
    Smem* s = reinterpret_cast<Smem*>(smem_raw);

    const int b    = blockIdx.x;
    const int tid  = threadIdx.x;
    const int lane = tid & 31;
    const int wid  = tid >> 5;         // 0..7
    const int mi   = wid & 1;          // m-subtile (16 rows)
    const int ni   = wid >> 1;         // n-subtile (32 cols), 0..3
    const int rq   = lane >> 2;        // 0..7  (fragment row)
    const int kq   = 2 * (lane & 3);   // 0,2,4,6 (fragment col pair)
    const int tskew = (b & 1) * 9;     // co-resident CTAs start 9 tiles apart

    // ---- pair table + zero scores ----
    for (int p = tid; p < P_; p += THREADS_) {
        int i = 0, base = 0;
        while (base + (F_ - 1 - i) <= p) { base += F_ - 1 - i; ++i; }
        int j = i + 1 + (p - base);
        s->pairs[p] = (unsigned short)((i << 8) | j);
        s->scores[p] = 0.f;
    }
    // ---- x[b] to smem ----
    const float4* xb = reinterpret_cast<const float4*>(x + (size_t)b * F_ * D_);
    for (int e = tid; e < F_ * D_ / 4; e += THREADS_) {
        int f = e >> 5, q = e & 31;
        *reinterpret_cast<float4*>(&s->xs[f][q * 4]) = xb[e];
    }
    if (tid < A_) {
        s->gnn_s[tid]  = gnn[(size_t)b * A_ + tid];
        s->bias_s[tid] = bias[tid];
    }
    // ---- W hi/lo bf16 tiles: W native [a][k], k-contiguous ----
    for (int e = tid; e < A_ * 16; e += THREADS_) {
        int a = e >> 4, kseg = e & 15, k0 = kseg * 8;
        const float4* wp = reinterpret_cast<const float4*>(W + a * D_ + k0);
        float4 w0 = wp[0], w1 = wp[1];
        uint4 hv, lv;
        bf16_split2(w0.x, w0.y, hv.x, lv.x);
        bf16_split2(w0.z, w0.w, hv.y, lv.y);
        bf16_split2(w1.x, w1.y, hv.z, lv.z);
        bf16_split2(w1.z, w1.w, hv.w, lv.w);
        *reinterpret_cast<uint4*>(&s->W_hi[a * SA + k0]) = hv;
        *reinterpret_cast<uint4*>(&s->W_lo[a * SA + k0]) = lv;
    }

    // ---- ldmatrix base addresses (byte, per-lane) ----
    // A x4 covers 16m x 16k
    const int arow = mi * 16 + (lane & 15);
    const int akb  = 8 * (lane >> 4);
    const uint32_t aAhi0 = smem_u32(&s->A_hi[arow * SA + akb]);
    const uint32_t aAlo0 = smem_u32(&s->A_lo[arow * SA + akb]);
    const uint32_t NSTEP = 16 * SA * 2;   // +16 B-rows, bytes
    // B x4 covers 16n x 16k
    const int brow = ni * 32 + (lane & 7) + 8 * (lane >> 4);
    const int bkb  = 8 * ((lane >> 3) & 1);
    const uint32_t bWhi0 = smem_u32(&s->W_hi[brow * SA + bkb]);
    const uint32_t bWlo0 = smem_u32(&s->W_lo[brow * SA + bkb]);

    // ==== main loop over 17 M-tiles of 32 pairs (skewed start per CTA parity) ====
    for (int t0 = 0; t0 < NT_TILES; ++t0) {
        int t = t0 + tskew;
        if (t >= NT_TILES) t -= NT_TILES;
        const int m0 = t * MT;
        __syncthreads();   // prior tile's A reads complete (and init done on t0=0)

        // ---- fill inner tile hi/lo: A[mloc][k] = xs[i][k]*xs[j][k] ----
        for (int e = tid; e < MT * 16; e += THREADS_) {
            int mloc = e >> 4, kseg = e & 15, k0 = kseg * 8;
            int m = m0 + mloc;
            uint4 hv = make_uint4(0, 0, 0, 0), lv = make_uint4(0, 0, 0, 0);
            if (m < P_) {
                unsigned short pr = s->pairs[m];
                const float4* xi = reinterpret_cast<const float4*>(&s->xs[pr >> 8][k0]);
                const float4* xj = reinterpret_cast<const float4*>(&s->xs[pr & 255][k0]);
                float4 a0 = xi[0], a1 = xi[1], c0 = xj[0], c1 = xj[1];
                bf16_split2(a0.x * c0.x, a0.y * c0.y, hv.x, lv.x);
                bf16_split2(a0.z * c0.z, a0.w * c0.w, hv.y, lv.y);
                bf16_split2(a1.x * c1.x, a1.y * c1.y, hv.z, lv.z);
                bf16_split2(a1.z * c1.z, a1.w * c1.w, hv.w, lv.w);
            }
            *reinterpret_cast<uint4*>(&s->A_hi[mloc * SA + k0]) = hv;
            *reinterpret_cast<uint4*>(&s->A_lo[mloc * SA + k0]) = lv;
        }
        __syncthreads();

        // ---- warp-level GEMM: warp owns 16 rows x 32 cols ----
        float acc[4][4];   // [n-frag][quad]
#pragma unroll
        for (int nf = 0; nf < 4; ++nf)
#pragma unroll
            for (int q = 0; q < 4; ++q) acc[nf][q] = 0.f;

#pragma unroll
        for (int ks = 0; ks < 8; ++ks) {
            const uint32_t kb = ks * 32;   // 16 bf16 = 32 bytes
            uint32_t ah[4], al[4], bh[2][4], bl[2][4];
            LDSM_X4(ah[0], ah[1], ah[2], ah[3], aAhi0 + kb);
            LDSM_X4(al[0], al[1], al[2], al[3], aAlo0 + kb);
            LDSM_X4(bh[0][0], bh[0][1], bh[0][2], bh[0][3], bWhi0 + kb);
            LDSM_X4(bh[1][0], bh[1][1], bh[1][2], bh[1][3], bWhi0 + NSTEP + kb);
            LDSM_X4(bl[0][0], bl[0][1], bl[0][2], bl[0][3], bWlo0 + kb);
            LDSM_X4(bl[1][0], bl[1][1], bl[1][2], bl[1][3], bWlo0 + NSTEP + kb);
#pragma unroll
            for (int jn = 0; jn < 2; ++jn) {
                mma_bf16(acc[2 * jn],     ah, bh[jn][0], bh[jn][1]);
                mma_bf16(acc[2 * jn],     ah, bl[jn][0], bl[jn][1]);
                mma_bf16(acc[2 * jn],     al, bh[jn][0], bh[jn][1]);
                mma_bf16(acc[2 * jn + 1], ah, bh[jn][2], bh[jn][3]);
                mma_bf16(acc[2 * jn + 1], ah, bl[jn][2], bl[jn][3]);
                mma_bf16(acc[2 * jn + 1], al, bh[jn][2], bh[jn][3]);
            }
        }

        // ---- epilogue: bias + relu + gnn dot over this warp's 32 cols ----
        float sc0 = 0.f, sc1 = 0.f;
#pragma unroll
        for (int nf = 0; nf < 4; ++nf) {
            const int n0 = ni * 32 + nf * 8 + kq;
            float g0 = s->gnn_s[n0], g1 = s->gnn_s[n0 + 1];
            float b0 = s->bias_s[n0], b1 = s->bias_s[n0 + 1];
            sc0 = fmaf(g0, fmaxf(acc[nf][0] + b0, 0.f), sc0);
            sc0 = fmaf(g1, fmaxf(acc[nf][1] + b1, 0.f), sc0);
            sc1 = fmaf(g0, fmaxf(acc[nf][2] + b0, 0.f), sc1);
            sc1 = fmaf(g1, fmaxf(acc[nf][3] + b1, 0.f), sc1);
        }
        sc0 += __shfl_xor_sync(0xffffffffu, sc0, 1);
        sc0 += __shfl_xor_sync(0xffffffffu, sc0, 2);
        sc1 += __shfl_xor_sync(0xffffffffu, sc1, 1);
        sc1 += __shfl_xor_sync(0xffffffffu, sc1, 2);
        if ((lane & 3) == 0) {
            int ma = m0 + mi * 16 + rq;   // 4 n-warps add per row
            if (ma < P_)     atomicAdd(&s->scores[ma],     sc0);
            if (ma + 8 < P_) atomicAdd(&s->scores[ma + 8], sc1);
        }
    }
    __syncthreads();

    // ==== softmax over scores[528] ====
    float lmax = -1e30f;
    for (int p = tid; p < P_; p += THREADS_) lmax = fmaxf(lmax, s->scores[p]);
#pragma unroll
    for (int o = 16; o; o >>= 1) lmax = fmaxf(lmax, __shfl_xor_sync(0xffffffffu, lmax, o));
    if (lane == 0) s->red[wid] = lmax;
    __syncthreads();
    if (tid < 32) {
        float v = (tid < 8) ? s->red[tid] : -1e30f;
#pragma unroll
        for (int o = 4; o; o >>= 1) v = fmaxf(v, __shfl_xor_sync(0xffffffffu, v, o));
        if (tid == 0) s->red[8] = v;
    }
    __syncthreads();
    const float mx = s->red[8];

    float lsum = 0.f;
    for (int p = tid; p < P_; p += THREADS_) {
        float e = __expf(s->scores[p] - mx);
        s->scores[p] = e;
        lsum += e;
    }
#pragma unroll
    for (int o = 16; o; o >>= 1) lsum += __shfl_xor_sync(0xffffffffu, lsum, o);
    if (lane == 0) s->red[wid] = lsum;
    __syncthreads();
    if (tid < 32) {
        float v = (tid < 8) ? s->red[tid] : 0.f;
#pragma unroll
        for (int o = 4; o; o >>= 1) v += __shfl_xor_sync(0xffffffffu, v, o);
        if (tid == 0) s->red[9] = v;
    }
    __syncthreads();
    const float scale = 100.f / s->red[9];

    // ==== attn_output[d] = scale * sum_p exp_p * xs[i][d]*xs[j][d] ====
    const int d    = tid & 127;
    const int half = tid >> 7;
    float accd = 0.f;
    const int pstart = half * (P_ / 2);
    for (int p = pstart; p < pstart + P_ / 2; ++p) {
        unsigned short pr = s->pairs[p];
        accd = fmaf(s->scores[p], s->xs[pr >> 8][d] * s->xs[pr & 255][d], accd);
    }
    s->part[half * 128 + d] = accd;
    __syncthreads();

    float* outb = out + (size_t)b * (A_ + D_);
    if (tid < 128) {
        outb[tid]       = s->gnn_s[tid];
        outb[128 + tid] = (s->part[tid] + s->part[128 + tid]) * scale;
    }
}

extern "C" void kernel_launch(void* const* d_in, const int* in_sizes, int n_in,
                              void* d_out, int out_size)
{
    const float* gnn  = (const float*)d_in[0];   // [B, 128]
    const float* x    = (const float*)d_in[1];   // [B, 33, 128]
    const float* W    = (const float*)d_in[2];   // [128, 128]
    const float* bias = (const float*)d_in[3];   // [128]
    float* out        = (float*)d_out;           // [B, 256]

    const int B = in_sizes[0] / A_;
    const int smem_bytes = (int)sizeof(Smem);

    cudaFuncSetAttribute(afm_kernel, cudaFuncAttributeMaxDynamicSharedMemorySize, smem_bytes);
    afm_kernel<<<B, THREADS_, smem_bytes>>>(gnn, x, W, bias, out);
}